// round 6
// baseline (speedup 1.0000x reference)
#include <cuda_runtime.h>
#include <cstdint>
#include <cfloat>

// Fused conv2d 3x3 SAME -> min over C_out -> *2 via pipelined mma.sync tf32.
// x: (32,64,128,128) f32, W: (128,64,3,3) f32, out: (32,1,128,128) f32
//
// Round 6: CTA tile 256x128 (2 output rows, shared B slab), 8 warps 4m x 2n,
// warp tile 64x64 -> fragment LDS bytes/MMA 192 -> 128, B traffic halved.
// B: pre-transformed W (fragment order, tf32-RNA) -> 8B cp.async, 3-stage.
// A: LDG(c+1) during compute(c), cvt+STS.128 after -> 2-stage, conflict-free.

#define TPB 256

static constexpr int A_SLAB = 3 * 16 * 32 * 16;   // 24576: [s][mtg16][lane]16B
static constexpr int B_SLAB = 3 * 16 * 32 * 8;    // 12288: [s][ntg16][lane]8B
static constexpr int RED_OFF = 2 * A_SLAB + 3 * B_SLAB;
static constexpr int SMEM_TOTAL = RED_OFF + 256 * 2 * 4;   // 90112

__device__ float W2g[24 * 3072];   // W fragment-ordered per chunk, tf32-rounded

__device__ __forceinline__ uint32_t smem_u32(const void* p) {
    uint32_t a;
    asm("{ .reg .u64 t; cvta.to.shared.u64 t, %1; cvt.u32.u64 %0, t; }" : "=r"(a) : "l"(p));
    return a;
}
__device__ __forceinline__ uint32_t f32_to_tf32(float v) {
    uint32_t r;
    asm("cvt.rna.tf32.f32 %0, %1;" : "=r"(r) : "f"(v));
    return r;
}
__device__ __forceinline__ void mma_tf32(float& d0, float& d1, float& d2, float& d3,
                                         uint32_t a0, uint32_t a1, uint32_t a2, uint32_t a3,
                                         uint32_t b0, uint32_t b1) {
    asm volatile(
        "mma.sync.aligned.m16n8k8.row.col.f32.tf32.tf32.f32 "
        "{%0,%1,%2,%3}, {%4,%5,%6,%7}, {%8,%9}, {%0,%1,%2,%3};"
        : "+f"(d0), "+f"(d1), "+f"(d2), "+f"(d3)
        : "r"(a0), "r"(a1), "r"(a2), "r"(a3), "r"(b0), "r"(b1));
}

// ---- pre-kernel: W (OIHW) -> fragment-ordered, tf32-rounded W2g ----
// W2g[c*3072 + j*2 + r]: j=(s*16+ntg)*32+L; oc=ntg*8+L/4; k=s*8+(L&3)+4r;
// chunk c: ic0=(c/3)*8, ky=c%3; within chunk k=(icl,kx), k=icl*3+kx.
__global__ void wxform_kernel(const float* __restrict__ Wt) {
    int f = blockIdx.x * TPB + threadIdx.x;
    if (f >= 24 * 3072) return;
    int c   = f / 3072;
    int rem = f - c * 3072;
    int j = rem >> 1, r = rem & 1;
    int L = j & 31, plane = j >> 5;
    int ntg = plane & 15, s = plane >> 4;
    int oc  = ntg * 8 + (L >> 2);
    int k   = s * 8 + (L & 3) + 4 * r;
    int icl = k / 3, kx = k - 3 * icl;
    int c3  = c / 3;
    int ic0 = c3 * 8, ky = c - 3 * c3;
    float v = Wt[oc * 576 + (ic0 + icl) * 9 + ky * 3 + kx];
    W2g[f] = __uint_as_float(f32_to_tf32(v));
}

__global__ void __launch_bounds__(TPB)
conv_min_mma3_kernel(const float* __restrict__ x,
                     float* __restrict__ out)
{
    extern __shared__ char smem[];
    const uint32_t sbA = smem_u32(smem);
    const uint32_t sbB = sbA + 2 * A_SLAB;
    const int tid    = threadIdx.x;
    const int lane   = tid & 31;
    const int wid    = tid >> 5;
    const int warp_m = wid >> 1;   // 0..3
    const int warp_n = wid & 1;    // 0..1
    const int y0 = blockIdx.x * 2;
    const int b  = blockIdx.y;
    const float* xb = x + (size_t)b * (64 * 128 * 128);

    // ---- per-thread A-fill constants: 6 slots of 16B each ----
    int a_off0[6], a_off1[6];      // icl*16384 + rowi*128 + px + kx - 1
    int a_row[6];                  // which of the 2 output rows
    bool pll[6], plh[6], phl[6], phh[6];
    uint32_t a_sts[6];
#pragma unroll
    for (int i = 0; i < 6; ++i) {
        int j = tid + TPB * i;
        int L = j & 31, plane = j >> 5;     // plane 0..47
        int mtg = plane & 15, s = plane >> 4;
        int m  = mtg * 16 + (L >> 2);       // 0..255
        int px = m & 127;
        int ri = m >> 7;                    // row 0/1
        int kl = s * 8 + (L & 3);
        int kh = kl + 4;
        int il = kl / 3, xl = kl - 3 * il;
        int ih = kh / 3, xh = kh - 3 * ih;
        a_off0[i] = il * 16384 + ri * 128 + px + xl - 1;
        a_off1[i] = ih * 16384 + ri * 128 + px + xh - 1;
        a_row[i]  = ri;
        pll[i] = !(px == 0 && xl == 0);
        plh[i] = !(px == 0 && xh == 0);
        phl[i] = !(px + 8 == 127 && xl == 2);
        phh[i] = !(px + 8 == 127 && xh == 2);
        a_sts[i] = (uint32_t)(((s * 16 + mtg) * 32 + L) * 16);
    }

    float acc[4][8][4];
#pragma unroll
    for (int mt = 0; mt < 4; ++mt)
#pragma unroll
        for (int nt = 0; nt < 8; ++nt)
#pragma unroll
            for (int r = 0; r < 4; ++r) acc[mt][nt][r] = 0.0f;

    // ---- prologue: issue B(0), B(1); fill A(0) ----
#pragma unroll
    for (int cc = 0; cc < 2; ++cc) {
        uint32_t dst = sbB + cc * B_SLAB;
        const float* src = W2g + cc * 3072;
#pragma unroll
        for (int i = 0; i < 6; ++i) {
            int j = tid + TPB * i;
            uint64_t g = __cvta_generic_to_global((const void*)(src + j * 2));
            asm volatile("cp.async.ca.shared.global [%0], [%1], 8;"
                         :: "r"(dst + (uint32_t)(j * 8)), "l"(g) : "memory");
        }
        asm volatile("cp.async.commit_group;" ::: "memory");
    }
    {   // A(0): chunk 0 -> ic0=0, ky=0, gybase=y0-1
        int gyb = y0 - 1;
        bool ok0 = (unsigned)gyb < 128u;
        bool ok1 = (unsigned)(gyb + 1) < 128u;
        const float* xrow = xb + gyb * 128;
#pragma unroll
        for (int i = 0; i < 6; ++i) {
            bool rk = a_row[i] ? ok1 : ok0;
            float v0 = 0.f, v1 = 0.f, v2 = 0.f, v3 = 0.f;
            if (rk && pll[i]) v0 = xrow[a_off0[i]];
            if (rk && phl[i]) v1 = xrow[a_off0[i] + 8];
            if (rk && plh[i]) v2 = xrow[a_off1[i]];
            if (rk && phh[i]) v3 = xrow[a_off1[i] + 8];
            asm volatile("st.shared.v4.b32 [%0], {%1,%2,%3,%4};"
                         :: "r"(sbA + a_sts[i]),
                            "r"(f32_to_tf32(v0)), "r"(f32_to_tf32(v1)),
                            "r"(f32_to_tf32(v2)), "r"(f32_to_tf32(v3)) : "memory");
        }
    }

    int bR = 0;
#pragma unroll 1
    for (int c = 0; c < 24; ++c) {
        asm volatile("cp.async.wait_group 1;" ::: "memory");
        __syncthreads();

        // issue B(c+2)
        if (c + 2 < 24) {
            int bW = bR - 1; if (bW < 0) bW += 3;
            uint32_t dst = sbB + (uint32_t)bW * B_SLAB;
            const float* src = W2g + (c + 2) * 3072;
#pragma unroll
            for (int i = 0; i < 6; ++i) {
                int j = tid + TPB * i;
                uint64_t g = __cvta_generic_to_global((const void*)(src + j * 2));
                asm volatile("cp.async.ca.shared.global [%0], [%1], 8;"
                             :: "r"(dst + (uint32_t)(j * 8)), "l"(g) : "memory");
            }
        }
        asm volatile("cp.async.commit_group;" ::: "memory");

        // prefetch A(c+1) into regs
        float av0[6], av1[6], av2[6], av3[6];
        if (c + 1 < 24) {
            int cn = c + 1;
            int c3 = cn / 3;
            int ic0 = c3 * 8, ky = cn - 3 * c3;
            int gyb = y0 + ky - 1;
            bool ok0 = (unsigned)gyb < 128u;
            bool ok1 = (unsigned)(gyb + 1) < 128u;
            const float* xrow = xb + ic0 * 16384 + gyb * 128;
#pragma unroll
            for (int i = 0; i < 6; ++i) {
                bool rk = a_row[i] ? ok1 : ok0;
                float v0 = 0.f, v1 = 0.f, v2 = 0.f, v3 = 0.f;
                if (rk && pll[i]) v0 = xrow[a_off0[i]];
                if (rk && phl[i]) v1 = xrow[a_off0[i] + 8];
                if (rk && plh[i]) v2 = xrow[a_off1[i]];
                if (rk && phh[i]) v3 = xrow[a_off1[i] + 8];
                av0[i] = v0; av1[i] = v1; av2[i] = v2; av3[i] = v3;
            }
        }

        // ---- compute chunk c (3 k-steps, 32 MMA each) ----
        const uint32_t aRd = sbA + (uint32_t)(c & 1) * A_SLAB;
        const uint32_t bRd = sbB + (uint32_t)bR * B_SLAB;
#pragma unroll
        for (int s = 0; s < 3; ++s) {
            uint32_t a0[4], a1[4], a2[4], a3[4];
#pragma unroll
            for (int mt = 0; mt < 4; ++mt) {
                uint32_t addr = aRd +
                    (uint32_t)(((s * 16 + warp_m * 4 + mt) * 32 + lane) * 16);
                asm volatile("ld.shared.v4.b32 {%0,%1,%2,%3}, [%4];"
                             : "=r"(a0[mt]), "=r"(a1[mt]), "=r"(a2[mt]), "=r"(a3[mt])
                             : "r"(addr));
            }
            uint32_t b0[8], b1[8];
#pragma unroll
            for (int nt = 0; nt < 8; ++nt) {
                uint32_t addr = bRd +
                    (uint32_t)(((s * 16 + warp_n * 8 + nt) * 32 + lane) * 8);
                asm volatile("ld.shared.v2.b32 {%0,%1}, [%2];"
                             : "=r"(b0[nt]), "=r"(b1[nt]) : "r"(addr));
            }
#pragma unroll
            for (int mt = 0; mt < 4; ++mt)
#pragma unroll
                for (int nt = 0; nt < 8; ++nt)
                    mma_tf32(acc[mt][nt][0], acc[mt][nt][1],
                             acc[mt][nt][2], acc[mt][nt][3],
                             a0[mt], a1[mt], a2[mt], a3[mt], b0[nt], b1[nt]);
        }

        // store prefetched A(c+1)
        if (c + 1 < 24) {
            const uint32_t aWr = sbA + (uint32_t)((c + 1) & 1) * A_SLAB;
#pragma unroll
            for (int i = 0; i < 6; ++i) {
                asm volatile("st.shared.v4.b32 [%0], {%1,%2,%3,%4};"
                             :: "r"(aWr + a_sts[i]),
                                "r"(f32_to_tf32(av0[i])), "r"(f32_to_tf32(av1[i])),
                                "r"(f32_to_tf32(av2[i])), "r"(f32_to_tf32(av3[i]))
                             : "memory");
            }
        }
        bR = (bR == 2) ? 0 : bR + 1;
    }

    // ---- epilogue: min over oc, *2, write 2 rows ----
    float rmin[4][2];
#pragma unroll
    for (int mt = 0; mt < 4; ++mt) {
        float lo = fminf(acc[mt][0][0], acc[mt][0][1]);
        float hi = fminf(acc[mt][0][2], acc[mt][0][3]);
#pragma unroll
        for (int nt = 1; nt < 8; ++nt) {
            lo = fminf(lo, fminf(acc[mt][nt][0], acc[mt][nt][1]));
            hi = fminf(hi, fminf(acc[mt][nt][2], acc[mt][nt][3]));
        }
        rmin[mt][0] = lo;
        rmin[mt][1] = hi;
    }
#pragma unroll
    for (int d = 1; d <= 2; d <<= 1)
#pragma unroll
        for (int mt = 0; mt < 4; ++mt)
#pragma unroll
            for (int h = 0; h < 2; ++h)
                rmin[mt][h] = fminf(rmin[mt][h],
                                    __shfl_xor_sync(0xffffffffu, rmin[mt][h], d));

    float* red = reinterpret_cast<float*>(smem + RED_OFF);
    __syncthreads();
    if ((lane & 3) == 0) {
        int g = lane >> 2;
#pragma unroll
        for (int mt = 0; mt < 4; ++mt)
#pragma unroll
            for (int h = 0; h < 2; ++h) {
                int m = warp_m * 64 + mt * 16 + h * 8 + g;   // 0..255
                red[m * 2 + warp_n] = rmin[mt][h];
            }
    }
    __syncthreads();
    {
        int m = tid;                       // 0..255
        float v = fminf(red[m * 2 + 0], red[m * 2 + 1]);
        int ri = m >> 7, px = m & 127;
        out[(size_t)b * 16384 + (y0 + ri) * 128 + px] = v * 2.0f;
    }
}

extern "C" void kernel_launch(void* const* d_in, const int* in_sizes, int n_in,
                              void* d_out, int out_size)
{
    const float* x  = (const float*)d_in[0];
    const float* Wt = (const float*)d_in[1];
    float* out = (float*)d_out;

    cudaFuncSetAttribute(conv_min_mma3_kernel,
                         cudaFuncAttributeMaxDynamicSharedMemorySize, SMEM_TOTAL);

    wxform_kernel<<<(24 * 3072 + TPB - 1) / TPB, TPB>>>(Wt);

    dim3 grid(64, 32);   // row-pairs x batch
    conv_min_mma3_kernel<<<grid, TPB, SMEM_TOTAL>>>(x, out);
}

// round 7
// speedup vs baseline: 1.2466x; 1.2466x over previous
#include <cuda_runtime.h>
#include <cstdint>
#include <cfloat>

// Fused conv2d 3x3 SAME -> min over C_out -> *2 via pipelined mma.sync tf32.
// x: (32,64,128,128) f32, W: (128,64,3,3) f32, out: (32,1,128,128) f32
//
// Round 7: R5 tiling (CTA 128x128, 8 warps 2m x 4n, warp 64x32, 2 CTA/SM)
// with chunk doubled to 48K (16 ic x 1 ky = 6 k-steps, 12 chunks) to halve
// per-chunk fixed costs. B: fragment-ordered W via 8B cp.async, 2-stage
// (issue at chunk end after a sync). A: LDG prefetch in two 12-load halves
// straddling the k-step groups (register-bounded), 2-stage STS.128.

#define TPB 256

static constexpr int A_SLAB = 6 * 8 * 32 * 16;    // 24576
static constexpr int B_SLAB = 6 * 16 * 32 * 8;    // 24576
static constexpr int RED_OFF = 2 * A_SLAB + 2 * B_SLAB;
static constexpr int SMEM_TOTAL = RED_OFF + 2048;  // 100352

__device__ float W2g[12 * 6144];   // W fragment-ordered per 48K chunk

__device__ __forceinline__ uint32_t smem_u32(const void* p) {
    uint32_t a;
    asm("{ .reg .u64 t; cvta.to.shared.u64 t, %1; cvt.u32.u64 %0, t; }" : "=r"(a) : "l"(p));
    return a;
}
__device__ __forceinline__ uint32_t f32_to_tf32(float v) {
    uint32_t r;
    asm("cvt.rna.tf32.f32 %0, %1;" : "=r"(r) : "f"(v));
    return r;
}
__device__ __forceinline__ void mma_tf32(float& d0, float& d1, float& d2, float& d3,
                                         uint32_t a0, uint32_t a1, uint32_t a2, uint32_t a3,
                                         uint32_t b0, uint32_t b1) {
    asm volatile(
        "mma.sync.aligned.m16n8k8.row.col.f32.tf32.tf32.f32 "
        "{%0,%1,%2,%3}, {%4,%5,%6,%7}, {%8,%9}, {%0,%1,%2,%3};"
        : "+f"(d0), "+f"(d1), "+f"(d2), "+f"(d3)
        : "r"(a0), "r"(a1), "r"(a2), "r"(a3), "r"(b0), "r"(b1));
}

// ---- pre-kernel: W (OIHW) -> fragment-ordered, tf32-rounded W2g ----
// W2g[c*6144 + j*2 + r]: j=(s*16+ntg)*32+L; oc=ntg*8+L/4; k=s*8+(L&3)+4r (0..47)
// chunk c: ic0=(c/3)*16, ky=c%3; k=(icl,kx), k=icl*3+kx.
__global__ void wxform_kernel(const float* __restrict__ Wt) {
    int f = blockIdx.x * TPB + threadIdx.x;
    if (f >= 12 * 6144) return;
    int c   = f / 6144;
    int rem = f - c * 6144;
    int j = rem >> 1, r = rem & 1;
    int L = j & 31, plane = j >> 5;
    int ntg = plane & 15, s = plane >> 4;
    int oc  = ntg * 8 + (L >> 2);
    int k   = s * 8 + (L & 3) + 4 * r;
    int icl = k / 3, kx = k - 3 * icl;
    int c3  = c / 3;
    int ic0 = c3 * 16, ky = c - 3 * c3;
    float v = Wt[oc * 576 + (ic0 + icl) * 9 + ky * 3 + kx];
    W2g[f] = __uint_as_float(f32_to_tf32(v));
}

// per-slot A prefetch: slot i covers k = i*8 + c4 (lo) and +4 (hi), pixel px
struct APre { float v0, v1, v2, v3; };

__device__ __forceinline__ APre a_load(const float* xrow, bool rowok,
                                       int i, int c4, int px) {
    int kl  = i * 8 + c4;
    int kh  = kl + 4;
    int il  = kl / 3, xl = kl - 3 * il;
    int ih  = kh / 3, xh = kh - 3 * ih;
    int o0  = il * 16384 + px + xl - 1;
    int o1  = ih * 16384 + px + xh - 1;
    APre a;
    a.v0 = (rowok && !(px == 0 && xl == 0))        ? xrow[o0]     : 0.0f;
    a.v1 = (rowok && !(px == 119 && xl == 2))      ? xrow[o0 + 8] : 0.0f;
    a.v2 = (rowok && !(px == 0 && xh == 0))        ? xrow[o1]     : 0.0f;
    a.v3 = (rowok && !(px == 119 && xh == 2))      ? xrow[o1 + 8] : 0.0f;
    return a;
}

__device__ __forceinline__ void a_store(uint32_t addr, const APre& a) {
    asm volatile("st.shared.v4.b32 [%0], {%1,%2,%3,%4};"
                 :: "r"(addr),
                    "r"(f32_to_tf32(a.v0)), "r"(f32_to_tf32(a.v1)),
                    "r"(f32_to_tf32(a.v2)), "r"(f32_to_tf32(a.v3)) : "memory");
}

__global__ void __launch_bounds__(TPB, 2)
conv_min_mma4_kernel(const float* __restrict__ x,
                     float* __restrict__ out)
{
    extern __shared__ char smem[];
    const uint32_t sbA = smem_u32(smem);
    const uint32_t sbB = sbA + 2 * A_SLAB;
    const int tid    = threadIdx.x;
    const int lane   = tid & 31;
    const int wid    = tid >> 5;
    const int warp_m = wid >> 2;   // 0..1
    const int warp_n = wid & 3;    // 0..3
    const int y = blockIdx.x;
    const int b = blockIdx.y;
    const float* xb = x + (size_t)b * (64 * 128 * 128);

    // A-fill per-thread constants (slot-invariant)
    const int c4  = tid & 3;                         // k low bits
    const int px  = ((tid >> 5) & 7) * 16 + ((tid >> 2) & 7);
    const uint32_t sts0 = (uint32_t)(((((tid >> 5) & 7) * 32) + lane) * 16);
    // slot i STS address: sbA(buf) + sts0 + i*4096

    float acc[4][4][4];
#pragma unroll
    for (int mt = 0; mt < 4; ++mt)
#pragma unroll
        for (int nt = 0; nt < 4; ++nt)
#pragma unroll
            for (int r = 0; r < 4; ++r) acc[mt][nt][r] = 0.0f;

    // ---- prologue: issue B(0), B(1); fill A(0) into buf 0 ----
#pragma unroll
    for (int cc = 0; cc < 2; ++cc) {
        uint32_t dst = sbB + cc * B_SLAB;
        const float* src = W2g + cc * 6144;
#pragma unroll
        for (int i = 0; i < 12; ++i) {
            int j = tid + TPB * i;
            uint64_t g = __cvta_generic_to_global((const void*)(src + j * 2));
            asm volatile("cp.async.ca.shared.global [%0], [%1], 8;"
                         :: "r"(dst + (uint32_t)(j * 8)), "l"(g) : "memory");
        }
        asm volatile("cp.async.commit_group;" ::: "memory");
    }
    {   // A(0): chunk 0 -> ic0=0, ky=0 -> gy=y-1
        int gy = y - 1;
        bool rowok = (unsigned)gy < 128u;
        const float* xrow = xb + gy * 128;
#pragma unroll
        for (int i = 0; i < 6; ++i) {
            APre a = a_load(xrow, rowok, i, c4, px);
            a_store(sbA + sts0 + (uint32_t)(i * 4096), a);
        }
    }

#pragma unroll 1
    for (int c = 0; c < 12; ++c) {
        // B(c) ready (<=1 group outstanding), A(c) stored by all threads
        asm volatile("cp.async.wait_group 1;" ::: "memory");
        __syncthreads();

        const uint32_t aRd = sbA + (uint32_t)(c & 1) * A_SLAB;
        const uint32_t bRd = sbB + (uint32_t)(c & 1) * B_SLAB;
        const uint32_t aWr = sbA + (uint32_t)((c + 1) & 1) * A_SLAB;

        // next-chunk A row info
        const int cn  = c + 1;
        const int c3n = cn / 3;
        const int gyn = y + (cn - 3 * c3n) - 1;
        const bool nok = (cn < 12) && ((unsigned)gyn < 128u);
        const float* xrown = xb + c3n * 16 * 16384 + gyn * 128;

        // prefetch A(c+1) half 1 (slots 0-2)
        APre ap[3];
        if (cn < 12) {
#pragma unroll
            for (int i = 0; i < 3; ++i) ap[i] = a_load(xrown, nok, i, c4, px);
        }

        // compute k-steps 0-2
#pragma unroll
        for (int s = 0; s < 3; ++s) {
            uint32_t a0[4], a1[4], a2[4], a3[4];
#pragma unroll
            for (int mt = 0; mt < 4; ++mt) {
                uint32_t addr = aRd +
                    (uint32_t)(((s * 8 + warp_m * 4 + mt) * 32 + lane) * 16);
                asm volatile("ld.shared.v4.b32 {%0,%1,%2,%3}, [%4];"
                             : "=r"(a0[mt]), "=r"(a1[mt]), "=r"(a2[mt]), "=r"(a3[mt])
                             : "r"(addr));
            }
            uint32_t b0[4], b1[4];
#pragma unroll
            for (int nt = 0; nt < 4; ++nt) {
                uint32_t addr = bRd +
                    (uint32_t)(((s * 16 + warp_n * 4 + nt) * 32 + lane) * 8);
                asm volatile("ld.shared.v2.b32 {%0,%1}, [%2];"
                             : "=r"(b0[nt]), "=r"(b1[nt]) : "r"(addr));
            }
#pragma unroll
            for (int mt = 0; mt < 4; ++mt)
#pragma unroll
                for (int nt = 0; nt < 4; ++nt)
                    mma_tf32(acc[mt][nt][0], acc[mt][nt][1],
                             acc[mt][nt][2], acc[mt][nt][3],
                             a0[mt], a1[mt], a2[mt], a3[mt], b0[nt], b1[nt]);
        }

        // store half 1, prefetch half 2 (slots 3-5)
        if (cn < 12) {
#pragma unroll
            for (int i = 0; i < 3; ++i)
                a_store(aWr + sts0 + (uint32_t)(i * 4096), ap[i]);
#pragma unroll
            for (int i = 0; i < 3; ++i) ap[i] = a_load(xrown, nok, i + 3, c4, px);
        }

        // compute k-steps 3-5
#pragma unroll
        for (int s = 3; s < 6; ++s) {
            uint32_t a0[4], a1[4], a2[4], a3[4];
#pragma unroll
            for (int mt = 0; mt < 4; ++mt) {
                uint32_t addr = aRd +
                    (uint32_t)(((s * 8 + warp_m * 4 + mt) * 32 + lane) * 16);
                asm volatile("ld.shared.v4.b32 {%0,%1,%2,%3}, [%4];"
                             : "=r"(a0[mt]), "=r"(a1[mt]), "=r"(a2[mt]), "=r"(a3[mt])
                             : "r"(addr));
            }
            uint32_t b0[4], b1[4];
#pragma unroll
            for (int nt = 0; nt < 4; ++nt) {
                uint32_t addr = bRd +
                    (uint32_t)(((s * 16 + warp_n * 4 + nt) * 32 + lane) * 8);
                asm volatile("ld.shared.v2.b32 {%0,%1}, [%2];"
                             : "=r"(b0[nt]), "=r"(b1[nt]) : "r"(addr));
            }
#pragma unroll
            for (int mt = 0; mt < 4; ++mt)
#pragma unroll
                for (int nt = 0; nt < 4; ++nt)
                    mma_tf32(acc[mt][nt][0], acc[mt][nt][1],
                             acc[mt][nt][2], acc[mt][nt][3],
                             a0[mt], a1[mt], a2[mt], a3[mt], b0[nt], b1[nt]);
        }

        // store half 2
        if (cn < 12) {
#pragma unroll
            for (int i = 0; i < 3; ++i)
                a_store(aWr + sts0 + (uint32_t)((i + 3) * 4096), ap[i]);
        }

        // all warps done reading B(c) buffer before overwrite by B(c+2)
        __syncthreads();
        if (c + 2 < 12) {
            uint32_t dst = sbB + (uint32_t)(c & 1) * B_SLAB;
            const float* src = W2g + (c + 2) * 6144;
#pragma unroll
            for (int i = 0; i < 12; ++i) {
                int j = tid + TPB * i;
                uint64_t g = __cvta_generic_to_global((const void*)(src + j * 2));
                asm volatile("cp.async.ca.shared.global [%0], [%1], 8;"
                             :: "r"(dst + (uint32_t)(j * 8)), "l"(g) : "memory");
            }
        }
        asm volatile("cp.async.commit_group;" ::: "memory");
    }

    // ---- epilogue: min over oc, *2, write ----
    float rmin[4][2];
#pragma unroll
    for (int mt = 0; mt < 4; ++mt) {
        float lo = fminf(acc[mt][0][0], acc[mt][0][1]);
        float hi = fminf(acc[mt][0][2], acc[mt][0][3]);
#pragma unroll
        for (int nt = 1; nt < 4; ++nt) {
            lo = fminf(lo, fminf(acc[mt][nt][0], acc[mt][nt][1]));
            hi = fminf(hi, fminf(acc[mt][nt][2], acc[mt][nt][3]));
        }
        rmin[mt][0] = lo;
        rmin[mt][1] = hi;
    }
#pragma unroll
    for (int d = 1; d <= 2; d <<= 1)
#pragma unroll
        for (int mt = 0; mt < 4; ++mt)
#pragma unroll
            for (int h = 0; h < 2; ++h)
                rmin[mt][h] = fminf(rmin[mt][h],
                                    __shfl_xor_sync(0xffffffffu, rmin[mt][h], d));

    float* red = reinterpret_cast<float*>(smem + RED_OFF);
    __syncthreads();
    if ((lane & 3) == 0) {
        int g = lane >> 2;
#pragma unroll
        for (int mt = 0; mt < 4; ++mt)
#pragma unroll
            for (int h = 0; h < 2; ++h) {
                int row = (warp_m * 4 + mt) * 16 + h * 8 + g;
                red[row * 4 + warp_n] = rmin[mt][h];
            }
    }
    __syncthreads();
    if (tid < 128) {
        float m = fminf(fminf(red[tid * 4 + 0], red[tid * 4 + 1]),
                        fminf(red[tid * 4 + 2], red[tid * 4 + 3]));
        out[(size_t)b * 16384 + y * 128 + tid] = m * 2.0f;
    }
}

extern "C" void kernel_launch(void* const* d_in, const int* in_sizes, int n_in,
                              void* d_out, int out_size)
{
    const float* x  = (const float*)d_in[0];
    const float* Wt = (const float*)d_in[1];
    float* out = (float*)d_out;

    cudaFuncSetAttribute(conv_min_mma4_kernel,
                         cudaFuncAttributeMaxDynamicSharedMemorySize, SMEM_TOTAL);

    wxform_kernel<<<(12 * 6144 + TPB - 1) / TPB, TPB>>>(Wt);

    dim3 grid(128, 32);   // rows x batch
    conv_min_mma4_kernel<<<grid, TPB, SMEM_TOTAL>>>(x, out);
}